// round 9
// baseline (speedup 1.0000x reference)
#include <cuda_runtime.h>
#include <cuda_fp16.h>
#include <cstdint>

// Problem constants
#define T_STEPS 512
#define BATCH   64
#define HID     512
#define GATES   1536   // 3*HID
#define NLAYERS 2

// Scratch (device globals; no allocation)
__device__ float g_gates[(size_t)T_STEPS * BATCH * GATES];   // input gates
__device__ float g_buf1[(size_t)T_STEPS * BATCH * HID];      // layer-1 output
__device__ uint32_t g_wfrag[(size_t)192 * 32 * 32 * 2];      // frag-ordered fp16 W_ih
__device__ __half g_hmir[2][BATCH][HID];                     // fp16 h mirror (dbl-buf)

// Per-batch-group sync state
struct alignas(128) BarSt { unsigned arrive; unsigned gen; unsigned pad[30]; };
__device__ BarSt g_bars[4];
struct alignas(32) Flag { unsigned v; unsigned pad[7]; };
__device__ Flag g_flags[4][32];   // [b-group][j-tile CTA]

__device__ __forceinline__ uint32_t pack_h2(float a, float b) {
    __half2 h = __floats2half2_rn(a, b);
    return *(uint32_t*)&h;
}

#define MMA_F16(acc, a0, a1, a2, a3, b0, b1)                                   \
    asm volatile(                                                              \
        "mma.sync.aligned.m16n8k16.row.col.f32.f16.f16.f32 "                   \
        "{%0,%1,%2,%3}, {%4,%5,%6,%7}, {%8,%9}, {%0,%1,%2,%3};\n"              \
        : "+f"((acc)[0]), "+f"((acc)[1]), "+f"((acc)[2]), "+f"((acc)[3])       \
        : "r"(a0), "r"(a1), "r"(a2), "r"(a3), "r"(b0), "r"(b1))

__device__ __forceinline__ void cp_async16(uint32_t dst, const void* src) {
    asm volatile("cp.async.cg.shared.global [%0], [%1], 16;" :: "r"(dst), "l"(src));
}
__device__ __forceinline__ unsigned ld_acq_gpu(unsigned* p) {
    unsigned v;
    asm volatile("ld.acquire.gpu.global.u32 %0, [%1];" : "=r"(v) : "l"(p) : "memory");
    return v;
}
__device__ __forceinline__ void st_rel_gpu(unsigned* p, unsigned v) {
    asm volatile("st.release.gpu.global.u32 [%0], %1;" :: "l"(p), "r"(v) : "memory");
}
__device__ __forceinline__ unsigned atom_add_rel_gpu(unsigned* p) {
    unsigned old;
    asm volatile("atom.add.release.gpu.global.u32 %0, [%1], 1;"
                 : "=r"(old) : "l"(p) : "memory");
    return old;
}

// ---------------------------------------------------------------------------
// Pre-convert W (1536 x 512 fp32) into fp16 MMA B-fragment order.
// ---------------------------------------------------------------------------
__global__ __launch_bounds__(256) void conv_wfrag_h(
    const float* __restrict__ W, uint32_t* __restrict__ F)
{
    int idx = blockIdx.x * 256 + threadIdx.x;
    int r    = idx & 1;
    int lane = (idx >> 1) & 31;
    int k16  = (idx >> 6) & 31;
    int nt   = idx >> 11;
    int n = nt * 8 + (lane >> 2);
    int k = k16 * 16 + (lane & 3) * 2 + r * 8;
    const float* p = W + (size_t)n * HID + k;
    F[idx] = pack_h2(p[0], p[1]);
}

// ---------------------------------------------------------------------------
// fp16 GEMM:  C[m,n] = sum_k A[m,k] * W[n,k] + bias[n]
// CTA tile 64x128; 8 warps; A staged pre-converted fp16 in SMEM.
// ---------------------------------------------------------------------------
#define APH 20

__global__ __launch_bounds__(256) void gemm_f16(
    const float* __restrict__ A, const uint32_t* __restrict__ Wf,
    const float* __restrict__ bias, float* __restrict__ C,
    int M, int N, int K)
{
    __shared__ uint32_t As[2][64][APH];

    const int bm  = blockIdx.y * 64;
    const int bnt = blockIdx.x * 16;
    const int tid = threadIdx.x;
    const int wid = tid >> 5;
    const int lane = tid & 31;
    const int wm = wid & 1;
    const int wn = wid >> 1;
    const int frow = lane >> 2;
    const int fk = lane & 3;

    float acc[2][4][4];
#pragma unroll
    for (int i = 0; i < 2; i++)
#pragma unroll
        for (int j = 0; j < 4; j++)
#pragma unroll
            for (int e = 0; e < 4; e++) acc[i][j][e] = 0.0f;

    const int lm = tid >> 2;
    const int lq = tid & 3;

    float4 pre[2];
    auto ldA = [&](int k0) {
#pragma unroll
        for (int it = 0; it < 2; it++) {
            int kq = lq * 2 + it;
            pre[it] = *(const float4*)(A + (size_t)(bm + lm) * K + k0 + kq * 4);
        }
    };
    auto stA = [&](int buf) {
#pragma unroll
        for (int it = 0; it < 2; it++) {
            int kq = lq * 2 + it;
            uint2 u = make_uint2(pack_h2(pre[it].x, pre[it].y),
                                 pack_h2(pre[it].z, pre[it].w));
            *(uint2*)&As[buf][lm][kq * 2] = u;
        }
    };

    ldA(0);
    stA(0);
    int buf = 0;

    for (int k0 = 0; k0 < K; k0 += 32) {
        __syncthreads();
        bool next = (k0 + 32 < K);
        if (next) ldA(k0 + 32);

#pragma unroll
        for (int sub = 0; sub < 2; sub++) {
            const int k16g = (k0 >> 4) + sub;
            uint32_t b0[4], b1[4];
#pragma unroll
            for (int j = 0; j < 4; j++) {
                size_t nt = (size_t)(bnt + wn * 4 + j);
                const uint2 v = __ldg((const uint2*)(Wf + ((nt * 32 + k16g) * 32 + lane) * 2));
                b0[j] = v.x; b1[j] = v.y;
            }
            uint32_t a[2][4];
#pragma unroll
            for (int i = 0; i < 2; i++) {
                int r0 = wm * 32 + i * 16 + frow;
                a[i][0] = As[buf][r0][sub * 8 + fk];
                a[i][1] = As[buf][r0 + 8][sub * 8 + fk];
                a[i][2] = As[buf][r0][sub * 8 + 4 + fk];
                a[i][3] = As[buf][r0 + 8][sub * 8 + 4 + fk];
            }
#pragma unroll
            for (int i = 0; i < 2; i++)
#pragma unroll
                for (int j = 0; j < 4; j++)
                    MMA_F16(acc[i][j], a[i][0], a[i][1], a[i][2], a[i][3],
                            b0[j], b1[j]);
        }
        if (next) stA(buf ^ 1);
        buf ^= 1;
    }

#pragma unroll
    for (int i = 0; i < 2; i++) {
        int mrow = bm + wm * 32 + i * 16 + frow;
#pragma unroll
        for (int j = 0; j < 4; j++) {
            int ncol = (bnt + wn * 4 + j) * 8 + fk * 2;
            float c0 = bias[ncol], c1 = bias[ncol + 1];
            *(float2*)(C + (size_t)mrow * N + ncol) =
                make_float2(acc[i][j][0] + c0, acc[i][j][1] + c1);
            *(float2*)(C + (size_t)(mrow + 8) * N + ncol) =
                make_float2(acc[i][j][2] + c0, acc[i][j][3] + c1);
        }
    }
}

// ---------------------------------------------------------------------------
// Counter barrier (used once at kernel end for flag reset)
// ---------------------------------------------------------------------------
__device__ __forceinline__ void group_barrier(int grp, unsigned nb)
{
    __syncthreads();
    if (threadIdx.x == 0) {
        unsigned gen0 = *(volatile unsigned*)&g_bars[grp].gen;
        unsigned prev = atom_add_rel_gpu(&g_bars[grp].arrive);
        if (prev == nb - 1) {
            *(volatile unsigned*)&g_bars[grp].arrive = 0;
            atom_add_rel_gpu(&g_bars[grp].gen);
        } else {
            while (ld_acq_gpu(&g_bars[grp].gen) == gen0) { }
        }
    }
    __syncthreads();
}

// ---------------------------------------------------------------------------
// Persistent recurrent kernel, fp16 MMA, fp16 h-mirror staging, flag barrier.
// grid = 128 CTAs = 32 j-tiles x 4 b-groups, 256 threads.
// ---------------------------------------------------------------------------
#define HSH_PITCH 520
#define PS_PITCH 50
#define REC_SMEM_BYTES (16 * HSH_PITCH * 2 + 8 * 16 * PS_PITCH * 4)

__global__ __launch_bounds__(256, 1) void gru_layer_mma(
    const float* __restrict__ gx_all,  // (T, B, 3H)
    const float* __restrict__ h0,      // (B, H)
    const float* __restrict__ Whh,     // (3H, H)
    const float* __restrict__ bhh,     // (3H)
    float* __restrict__ out)           // (T, B, H); out[t] doubles as h_t
{
    extern __shared__ float sm[];
    __half* h_sh = (__half*)sm;                       // [16][HSH_PITCH]
    float* Ps = sm + (16 * HSH_PITCH * 2) / 4;        // [8][16][PS_PITCH]

    const int jt = blockIdx.x & 31;
    const int bt = blockIdx.x >> 5;
    const int j0 = jt * 16;
    const int b0 = bt * 16;
    const int tid = threadIdx.x;
    const int w = tid >> 5;
    const int lane = tid & 31;

    // W_hh fp16 fragments into registers (once).
    uint32_t wb0[6][4], wb1[6][4];
    {
        const int colq = lane >> 2;
        const int kq2 = (lane & 3) * 2;
#pragma unroll
        for (int tl = 0; tl < 6; tl++) {
            int g = tl >> 1;
            int col = j0 + (tl & 1) * 8 + colq;
            const float* wrow = Whh + (size_t)(g * HID + col) * HID;
#pragma unroll
            for (int kk = 0; kk < 4; kk++) {
                int ks = (w * 4 + kk) * 16 + kq2;
                wb0[tl][kk] = pack_h2(wrow[ks], wrow[ks + 1]);
                wb1[tl][kk] = pack_h2(wrow[ks + 8], wrow[ks + 9]);
            }
        }
    }

    const int gb = tid >> 4;
    const int gj = tid & 15;
    const int bg_g = b0 + gb;
    const int jg_g = j0 + gj;
    const float br_ = bhh[jg_g];
    const float bz_ = bhh[HID + jg_g];
    const float bn_ = bhh[2 * HID + jg_g];

    const int frow = lane >> 2;
    const int fk = lane & 3;

    // prefetch t=0 input-side gates
    const float* gxp = gx_all + (size_t)bg_g * GATES;
    float xr = __ldg(gxp + jg_g);
    float xz = __ldg(gxp + HID + jg_g);
    float xn = __ldg(gxp + 2 * HID + jg_g);

    for (int t = 0; t < T_STEPS; t++) {
        const float* hprev = (t == 0) ? h0 : out + (size_t)(t - 1) * BATCH * HID;

        // exact fp32 h_prev for the blend (coalesced small read)
        float hpv = __ldg(hprev + (size_t)bg_g * HID + jg_g);

        if (t == 0) {
            // stage from fp32 h0 with conversion
#pragma unroll
            for (int q = 0; q < 8; q++) {
                int f = q * 256 + tid;
                int rr = f >> 7;
                int c4 = f & 127;
                float4 v = *((const float4*)(h0 + (size_t)(b0 + rr) * HID) + c4);
                uint2 u = make_uint2(pack_h2(v.x, v.y), pack_h2(v.z, v.w));
                *(uint2*)&h_sh[rr * HSH_PITCH + c4 * 4] = u;
            }
        } else {
            // stage fp16 mirror via cp.async: 16 rows x 64 16B-chunks
            const __half* mir = &g_hmir[(t - 1) & 1][b0][0];
#pragma unroll
            for (int q = 0; q < 4; q++) {
                int f = q * 256 + tid;
                int rr = f >> 6;
                int c = f & 63;
                uint32_t dst = (uint32_t)__cvta_generic_to_shared(
                    &h_sh[rr * HSH_PITCH + c * 8]);
                cp_async16(dst, mir + (size_t)rr * HID + c * 8);
            }
            asm volatile("cp.async.commit_group;");
            asm volatile("cp.async.wait_group 0;");
        }
        __syncthreads();

        // MMA over this warp's k-slice: 4 k16-steps x 6 n-tiles
        float acc[6][4];
#pragma unroll
        for (int tl = 0; tl < 6; tl++) {
            acc[tl][0] = 0.f; acc[tl][1] = 0.f; acc[tl][2] = 0.f; acc[tl][3] = 0.f;
        }
#pragma unroll
        for (int kk = 0; kk < 4; kk++) {
            int kbase = (w * 4 + kk) * 16;
            uint32_t a0 = *(const uint32_t*)&h_sh[frow * HSH_PITCH + kbase + fk * 2];
            uint32_t a1 = *(const uint32_t*)&h_sh[(frow + 8) * HSH_PITCH + kbase + fk * 2];
            uint32_t a2 = *(const uint32_t*)&h_sh[frow * HSH_PITCH + kbase + 8 + fk * 2];
            uint32_t a3 = *(const uint32_t*)&h_sh[(frow + 8) * HSH_PITCH + kbase + 8 + fk * 2];
#pragma unroll
            for (int tl = 0; tl < 6; tl++)
                MMA_F16(acc[tl], a0, a1, a2, a3, wb0[tl][kk], wb1[tl][kk]);
        }
        {
            int m = lane >> 2;
            int ncb = 2 * (lane & 3);
#pragma unroll
            for (int tl = 0; tl < 6; tl++) {
                *(float2*)&Ps[(w * 16 + m) * PS_PITCH + tl * 8 + ncb] =
                    make_float2(acc[tl][0], acc[tl][1]);
                *(float2*)&Ps[(w * 16 + m + 8) * PS_PITCH + tl * 8 + ncb] =
                    make_float2(acc[tl][2], acc[tl][3]);
            }
        }
        __syncthreads();

        // reduce 8 partials + gating
        float hr = 0.f, hz = 0.f, hn = 0.f;
#pragma unroll
        for (int ww = 0; ww < 8; ww++) {
            const float* p = &Ps[(ww * 16 + gb) * PS_PITCH];
            hr += p[gj];
            hz += p[16 + gj];
            hn += p[32 + gj];
        }
        float r = 1.0f / (1.0f + __expf(-(xr + hr + br_)));
        float z = 1.0f / (1.0f + __expf(-(xz + hz + bz_)));
        float n = tanhf(xn + r * (hn + bn_));
        float hnew = (1.0f - z) * n + z * hpv;

        out[(size_t)t * BATCH * HID + (size_t)bg_g * HID + jg_g] = hnew;
        g_hmir[t & 1][bg_g][jg_g] = __float2half_rn(hnew);

        // prefetch next step's input-side gates (overlaps barrier wait)
        int tn = (t + 1 < T_STEPS) ? t + 1 : t;
        const float* gxn = gx_all + (size_t)tn * BATCH * GATES + (size_t)bg_g * GATES;
        xr = __ldg(gxn + jg_g);
        xz = __ldg(gxn + HID + jg_g);
        xn = __ldg(gxn + 2 * HID + jg_g);

        if (t != T_STEPS - 1) {
            // flag barrier: fire-and-forget release, parallel polls
            __syncthreads();
            if (tid == 0) st_rel_gpu(&g_flags[bt][jt].v, (unsigned)(t + 1));
            if (tid < 32) {
                unsigned* fp = &g_flags[bt][tid].v;
                int spins = 0;
                while ((int)ld_acq_gpu(fp) < t + 1) {
                    if (++spins > 4) __nanosleep(64);
                }
            }
            __syncthreads();
        }
    }

    // end: reset flags for next launch/replay (behind a counter barrier)
    group_barrier(bt, 32);
    if (jt == 0 && tid < 32) g_flags[bt][tid].v = 0;
}

// ---------------------------------------------------------------------------
extern "C" void kernel_launch(void* const* d_in, const int* in_sizes, int n_in,
                              void* d_out, int out_size)
{
    const float* x    = (const float*)d_in[0];
    const float* h0   = (const float*)d_in[1];
    const float* w_ih = (const float*)d_in[2];
    const float* w_hh = (const float*)d_in[3];
    const float* b_ih = (const float*)d_in[4];
    const float* b_hh = (const float*)d_in[5];
    float* out_final  = (float*)d_out;

    float* gates; float* buf1; uint32_t* wfrag;
    cudaGetSymbolAddress((void**)&gates, g_gates);
    cudaGetSymbolAddress((void**)&buf1, g_buf1);
    cudaGetSymbolAddress((void**)&wfrag, g_wfrag);

    static int smem_configured = 0;
    if (!smem_configured) {
        cudaFuncSetAttribute(gru_layer_mma,
                             cudaFuncAttributeMaxDynamicSharedMemorySize, REC_SMEM_BYTES);
        smem_configured = 1;
    }

    const int M = T_STEPS * BATCH;
    const int K = HID;

    for (int l = 0; l < NLAYERS; l++) {
        const float* inp   = (l == 0) ? x : buf1;
        float*       out   = (l == NLAYERS - 1) ? out_final : buf1;
        const float* wih_l = w_ih + (size_t)l * GATES * HID;
        const float* whh_l = w_hh + (size_t)l * GATES * HID;
        const float* bih_l = b_ih + (size_t)l * GATES;
        const float* bhh_l = b_hh + (size_t)l * GATES;
        const float* h0_l  = h0 + (size_t)l * BATCH * HID;

        conv_wfrag_h<<<1536, 256>>>(wih_l, wfrag);

        dim3 ggrid(GATES / 128, M / 64);
        gemm_f16<<<ggrid, 256>>>(inp, wfrag, bih_l, gates, M, GATES, K);

        gru_layer_mma<<<128, 256, REC_SMEM_BYTES>>>(gates, h0_l, whh_l, bhh_l, out);
    }
}

// round 10
// speedup vs baseline: 1.0625x; 1.0625x over previous
#include <cuda_runtime.h>
#include <cuda_fp16.h>
#include <cstdint>

// Problem constants
#define T_STEPS 512
#define BATCH   64
#define HID     512
#define GATES   1536   // 3*HID
#define NLAYERS 2

// Scratch (device globals; no allocation)
__device__ float g_gates[(size_t)T_STEPS * BATCH * GATES];   // input gates
__device__ float g_buf1[(size_t)T_STEPS * BATCH * HID];      // layer-1 output
__device__ uint32_t g_wfrag[(size_t)192 * 32 * 32 * 2];      // frag-ordered fp16 W_ih
__device__ __half g_hmir[2][BATCH][HID];                     // fp16 h mirror (dbl-buf)

// Per-batch-group software barriers (4 groups x 32 CTAs)
struct alignas(128) BarSt { unsigned arrive; unsigned gen; unsigned pad[30]; };
__device__ BarSt g_bars[4];

__device__ __forceinline__ uint32_t pack_h2(float a, float b) {
    __half2 h = __floats2half2_rn(a, b);
    return *(uint32_t*)&h;
}

#define MMA_F16(acc, a0, a1, a2, a3, b0, b1)                                   \
    asm volatile(                                                              \
        "mma.sync.aligned.m16n8k16.row.col.f32.f16.f16.f32 "                   \
        "{%0,%1,%2,%3}, {%4,%5,%6,%7}, {%8,%9}, {%0,%1,%2,%3};\n"              \
        : "+f"((acc)[0]), "+f"((acc)[1]), "+f"((acc)[2]), "+f"((acc)[3])       \
        : "r"(a0), "r"(a1), "r"(a2), "r"(a3), "r"(b0), "r"(b1))

__device__ __forceinline__ void cp_async16(uint32_t dst, const void* src) {
    asm volatile("cp.async.cg.shared.global [%0], [%1], 16;" :: "r"(dst), "l"(src));
}
__device__ __forceinline__ unsigned ld_acq_gpu(unsigned* p) {
    unsigned v;
    asm volatile("ld.acquire.gpu.global.u32 %0, [%1];" : "=r"(v) : "l"(p) : "memory");
    return v;
}
__device__ __forceinline__ unsigned atom_add_rel_gpu(unsigned* p) {
    unsigned old;
    asm volatile("atom.add.release.gpu.global.u32 %0, [%1], 1;"
                 : "=r"(old) : "l"(p) : "memory");
    return old;
}

// ---------------------------------------------------------------------------
// Pre-convert W (1536 x 512 fp32) into fp16 MMA B-fragment order.
// ---------------------------------------------------------------------------
__global__ __launch_bounds__(256) void conv_wfrag_h(
    const float* __restrict__ W, uint32_t* __restrict__ F)
{
    int idx = blockIdx.x * 256 + threadIdx.x;
    int r    = idx & 1;
    int lane = (idx >> 1) & 31;
    int k16  = (idx >> 6) & 31;
    int nt   = idx >> 11;
    int n = nt * 8 + (lane >> 2);
    int k = k16 * 16 + (lane & 3) * 2 + r * 8;
    const float* p = W + (size_t)n * HID + k;
    F[idx] = pack_h2(p[0], p[1]);
}

// ---------------------------------------------------------------------------
// fp16 GEMM:  C[m,n] = sum_k A[m,k] * W[n,k] + bias[n]
// CTA tile 64x128; 8 warps; A staged pre-converted fp16 in SMEM.
// ---------------------------------------------------------------------------
#define APH 20

__global__ __launch_bounds__(256) void gemm_f16(
    const float* __restrict__ A, const uint32_t* __restrict__ Wf,
    const float* __restrict__ bias, float* __restrict__ C,
    int M, int N, int K)
{
    __shared__ uint32_t As[2][64][APH];

    const int bm  = blockIdx.y * 64;
    const int bnt = blockIdx.x * 16;
    const int tid = threadIdx.x;
    const int wid = tid >> 5;
    const int lane = tid & 31;
    const int wm = wid & 1;
    const int wn = wid >> 1;
    const int frow = lane >> 2;
    const int fk = lane & 3;

    float acc[2][4][4];
#pragma unroll
    for (int i = 0; i < 2; i++)
#pragma unroll
        for (int j = 0; j < 4; j++)
#pragma unroll
            for (int e = 0; e < 4; e++) acc[i][j][e] = 0.0f;

    const int lm = tid >> 2;
    const int lq = tid & 3;

    float4 pre[2];
    auto ldA = [&](int k0) {
#pragma unroll
        for (int it = 0; it < 2; it++) {
            int kq = lq * 2 + it;
            pre[it] = *(const float4*)(A + (size_t)(bm + lm) * K + k0 + kq * 4);
        }
    };
    auto stA = [&](int buf) {
#pragma unroll
        for (int it = 0; it < 2; it++) {
            int kq = lq * 2 + it;
            uint2 u = make_uint2(pack_h2(pre[it].x, pre[it].y),
                                 pack_h2(pre[it].z, pre[it].w));
            *(uint2*)&As[buf][lm][kq * 2] = u;
        }
    };

    ldA(0);
    stA(0);
    int buf = 0;

    for (int k0 = 0; k0 < K; k0 += 32) {
        __syncthreads();
        bool next = (k0 + 32 < K);
        if (next) ldA(k0 + 32);

#pragma unroll
        for (int sub = 0; sub < 2; sub++) {
            const int k16g = (k0 >> 4) + sub;
            uint32_t b0[4], b1[4];
#pragma unroll
            for (int j = 0; j < 4; j++) {
                size_t nt = (size_t)(bnt + wn * 4 + j);
                const uint2 v = __ldg((const uint2*)(Wf + ((nt * 32 + k16g) * 32 + lane) * 2));
                b0[j] = v.x; b1[j] = v.y;
            }
            uint32_t a[2][4];
#pragma unroll
            for (int i = 0; i < 2; i++) {
                int r0 = wm * 32 + i * 16 + frow;
                a[i][0] = As[buf][r0][sub * 8 + fk];
                a[i][1] = As[buf][r0 + 8][sub * 8 + fk];
                a[i][2] = As[buf][r0][sub * 8 + 4 + fk];
                a[i][3] = As[buf][r0 + 8][sub * 8 + 4 + fk];
            }
#pragma unroll
            for (int i = 0; i < 2; i++)
#pragma unroll
                for (int j = 0; j < 4; j++)
                    MMA_F16(acc[i][j], a[i][0], a[i][1], a[i][2], a[i][3],
                            b0[j], b1[j]);
        }
        if (next) stA(buf ^ 1);
        buf ^= 1;
    }

#pragma unroll
    for (int i = 0; i < 2; i++) {
        int mrow = bm + wm * 32 + i * 16 + frow;
#pragma unroll
        for (int j = 0; j < 4; j++) {
            int ncol = (bnt + wn * 4 + j) * 8 + fk * 2;
            float c0 = bias[ncol], c1 = bias[ncol + 1];
            *(float2*)(C + (size_t)mrow * N + ncol) =
                make_float2(acc[i][j][0] + c0, acc[i][j][1] + c1);
            *(float2*)(C + (size_t)(mrow + 8) * N + ncol) =
                make_float2(acc[i][j][2] + c0, acc[i][j][3] + c1);
        }
    }
}

// ---------------------------------------------------------------------------
// Per-batch-group grid barrier (32 CTAs per group), acquire/release atomics.
// ---------------------------------------------------------------------------
__device__ __forceinline__ void group_barrier(int grp, unsigned nb)
{
    __syncthreads();
    if (threadIdx.x == 0) {
        unsigned gen0 = *(volatile unsigned*)&g_bars[grp].gen;
        unsigned prev = atom_add_rel_gpu(&g_bars[grp].arrive);
        if (prev == nb - 1) {
            *(volatile unsigned*)&g_bars[grp].arrive = 0;
            atom_add_rel_gpu(&g_bars[grp].gen);
        } else {
            while (ld_acq_gpu(&g_bars[grp].gen) == gen0) { }
        }
    }
    __syncthreads();
}

// ---------------------------------------------------------------------------
// Persistent recurrent kernel, fp16 MMA (m16n8k16), fp16 mirror staging.
// grid = 128 CTAs = 32 j-tiles (16 hidden) x 4 b-groups (16 batch), 256 thr.
// W_hh fragments register-resident; h staged from fp16 mirror via cp.async.
// ---------------------------------------------------------------------------
#define HSH_PITCH 520          // halfs per row; (520/2) % 32 == 4 -> conflict-free
#define PS_PITCH 50
#define REC_SMEM_BYTES (16 * HSH_PITCH * 2 + 8 * 16 * PS_PITCH * 4)

__global__ __launch_bounds__(256, 1) void gru_layer_mma(
    const float* __restrict__ gx_all,  // (T, B, 3H)
    const float* __restrict__ h0,      // (B, H)
    const float* __restrict__ Whh,     // (3H, H)
    const float* __restrict__ bhh,     // (3H)
    float* __restrict__ out)           // (T, B, H); out[t] doubles as h_t
{
    extern __shared__ float sm[];
    __half* h_sh = (__half*)sm;                       // [16][HSH_PITCH]
    float* Ps = sm + (16 * HSH_PITCH * 2) / 4;        // [8][16][PS_PITCH]

    const int jt = blockIdx.x & 31;
    const int bt = blockIdx.x >> 5;
    const int j0 = jt * 16;
    const int b0 = bt * 16;
    const int tid = threadIdx.x;
    const int w = tid >> 5;
    const int lane = tid & 31;

    // W_hh fp16 fragments into registers (once). Warp w owns k16-steps
    // [w*4, w*4+4).
    uint32_t wb0[6][4], wb1[6][4];
    {
        const int colq = lane >> 2;
        const int kq2 = (lane & 3) * 2;
#pragma unroll
        for (int tl = 0; tl < 6; tl++) {
            int g = tl >> 1;
            int col = j0 + (tl & 1) * 8 + colq;
            const float* wrow = Whh + (size_t)(g * HID + col) * HID;
#pragma unroll
            for (int kk = 0; kk < 4; kk++) {
                int ks = (w * 4 + kk) * 16 + kq2;
                wb0[tl][kk] = pack_h2(wrow[ks], wrow[ks + 1]);
                wb1[tl][kk] = pack_h2(wrow[ks + 8], wrow[ks + 9]);
            }
        }
    }

    const int gb = tid >> 4;
    const int gj = tid & 15;
    const int bg_g = b0 + gb;
    const int jg_g = j0 + gj;
    const float br_ = bhh[jg_g];
    const float bz_ = bhh[HID + jg_g];
    const float bn_ = bhh[2 * HID + jg_g];

    const int frow = lane >> 2;
    const int fk = lane & 3;

    // prefetch t=0 input-side gates
    const float* gxp = gx_all + (size_t)bg_g * GATES;
    float xr = __ldg(gxp + jg_g);
    float xz = __ldg(gxp + HID + jg_g);
    float xn = __ldg(gxp + 2 * HID + jg_g);

    for (int t = 0; t < T_STEPS; t++) {
        const float* hprev = (t == 0) ? h0 : out + (size_t)(t - 1) * BATCH * HID;

        // exact fp32 h_prev for the blend (coalesced small read)
        float hpv = __ldg(hprev + (size_t)bg_g * HID + jg_g);

        if (t == 0) {
            // stage from fp32 h0 with conversion (same rounding as mirror path)
#pragma unroll
            for (int q = 0; q < 8; q++) {
                int f = q * 256 + tid;
                int rr = f >> 7;
                int c4 = f & 127;
                float4 v = *((const float4*)(h0 + (size_t)(b0 + rr) * HID) + c4);
                uint2 u = make_uint2(pack_h2(v.x, v.y), pack_h2(v.z, v.w));
                *(uint2*)&h_sh[rr * HSH_PITCH + c4 * 4] = u;
            }
        } else {
            // stage fp16 mirror via cp.async: 16 rows x 64 16B-chunks (16 KB)
            const __half* mir = &g_hmir[(t - 1) & 1][b0][0];
#pragma unroll
            for (int q = 0; q < 4; q++) {
                int f = q * 256 + tid;
                int rr = f >> 6;
                int c = f & 63;
                uint32_t dst = (uint32_t)__cvta_generic_to_shared(
                    &h_sh[rr * HSH_PITCH + c * 8]);
                cp_async16(dst, mir + (size_t)rr * HID + c * 8);
            }
            asm volatile("cp.async.commit_group;");
            asm volatile("cp.async.wait_group 0;");
        }
        __syncthreads();

        // MMA over this warp's k-slice: 4 k16-steps x 6 n-tiles
        float acc[6][4];
#pragma unroll
        for (int tl = 0; tl < 6; tl++) {
            acc[tl][0] = 0.f; acc[tl][1] = 0.f; acc[tl][2] = 0.f; acc[tl][3] = 0.f;
        }
#pragma unroll
        for (int kk = 0; kk < 4; kk++) {
            int kbase = (w * 4 + kk) * 16;
            uint32_t a0 = *(const uint32_t*)&h_sh[frow * HSH_PITCH + kbase + fk * 2];
            uint32_t a1 = *(const uint32_t*)&h_sh[(frow + 8) * HSH_PITCH + kbase + fk * 2];
            uint32_t a2 = *(const uint32_t*)&h_sh[frow * HSH_PITCH + kbase + 8 + fk * 2];
            uint32_t a3 = *(const uint32_t*)&h_sh[(frow + 8) * HSH_PITCH + kbase + 8 + fk * 2];
#pragma unroll
            for (int tl = 0; tl < 6; tl++)
                MMA_F16(acc[tl], a0, a1, a2, a3, wb0[tl][kk], wb1[tl][kk]);
        }
        {
            int m = lane >> 2;
            int ncb = 2 * (lane & 3);
#pragma unroll
            for (int tl = 0; tl < 6; tl++) {
                *(float2*)&Ps[(w * 16 + m) * PS_PITCH + tl * 8 + ncb] =
                    make_float2(acc[tl][0], acc[tl][1]);
                *(float2*)&Ps[(w * 16 + m + 8) * PS_PITCH + tl * 8 + ncb] =
                    make_float2(acc[tl][2], acc[tl][3]);
            }
        }
        __syncthreads();

        // reduce 8 partials + gating
        float hr = 0.f, hz = 0.f, hn = 0.f;
#pragma unroll
        for (int ww = 0; ww < 8; ww++) {
            const float* p = &Ps[(ww * 16 + gb) * PS_PITCH];
            hr += p[gj];
            hz += p[16 + gj];
            hn += p[32 + gj];
        }
        float r = 1.0f / (1.0f + __expf(-(xr + hr + br_)));
        float z = 1.0f / (1.0f + __expf(-(xz + hz + bz_)));
        float n = tanhf(xn + r * (hn + bn_));
        float hnew = (1.0f - z) * n + z * hpv;

        out[(size_t)t * BATCH * HID + (size_t)bg_g * HID + jg_g] = hnew;
        g_hmir[t & 1][bg_g][jg_g] = __float2half_rn(hnew);

        // prefetch next step's input-side gates (hides L2 behind barrier wait)
        int tn = (t + 1 < T_STEPS) ? t + 1 : t;
        const float* gxn = gx_all + (size_t)tn * BATCH * GATES + (size_t)bg_g * GATES;
        xr = __ldg(gxn + jg_g);
        xz = __ldg(gxn + HID + jg_g);
        xn = __ldg(gxn + 2 * HID + jg_g);

        if (t != T_STEPS - 1)
            group_barrier(bt, 32);
    }
}

// ---------------------------------------------------------------------------
extern "C" void kernel_launch(void* const* d_in, const int* in_sizes, int n_in,
                              void* d_out, int out_size)
{
    const float* x    = (const float*)d_in[0];
    const float* h0   = (const float*)d_in[1];
    const float* w_ih = (const float*)d_in[2];
    const float* w_hh = (const float*)d_in[3];
    const float* b_ih = (const float*)d_in[4];
    const float* b_hh = (const float*)d_in[5];
    float* out_final  = (float*)d_out;

    float* gates; float* buf1; uint32_t* wfrag;
    cudaGetSymbolAddress((void**)&gates, g_gates);
    cudaGetSymbolAddress((void**)&buf1, g_buf1);
    cudaGetSymbolAddress((void**)&wfrag, g_wfrag);

    static int smem_configured = 0;
    if (!smem_configured) {
        cudaFuncSetAttribute(gru_layer_mma,
                             cudaFuncAttributeMaxDynamicSharedMemorySize, REC_SMEM_BYTES);
        smem_configured = 1;
    }

    const int M = T_STEPS * BATCH;
    const int K = HID;

    for (int l = 0; l < NLAYERS; l++) {
        const float* inp   = (l == 0) ? x : buf1;
        float*       out   = (l == NLAYERS - 1) ? out_final : buf1;
        const float* wih_l = w_ih + (size_t)l * GATES * HID;
        const float* whh_l = w_hh + (size_t)l * GATES * HID;
        const float* bih_l = b_ih + (size_t)l * GATES;
        const float* bhh_l = b_hh + (size_t)l * GATES;
        const float* h0_l  = h0 + (size_t)l * BATCH * HID;

        conv_wfrag_h<<<1536, 256>>>(wih_l, wfrag);

        dim3 ggrid(GATES / 128, M / 64);
        gemm_f16<<<ggrid, 256>>>(inp, wfrag, bih_l, gates, M, GATES, K);

        gru_layer_mma<<<128, 256, REC_SMEM_BYTES>>>(gates, h0_l, whh_l, bhh_l, out);
    }
}

// round 12
// speedup vs baseline: 1.4679x; 1.3815x over previous
#include <cuda_runtime.h>
#include <cuda_fp16.h>
#include <cstdint>

// Problem constants
#define T_STEPS 512
#define BATCH   64
#define HID     512
#define GATES   1536   // 3*HID
#define NLAYERS 2

// Scratch (device globals; no allocation)
__device__ float g_gates[(size_t)T_STEPS * BATCH * GATES];   // input gates
__device__ float g_buf1[(size_t)T_STEPS * BATCH * HID];      // layer-1 output
__device__ uint32_t g_wfrag[(size_t)192 * 32 * 32 * 2];      // frag-ordered fp16 W_ih
__device__ __half g_hmir[2][BATCH][HID];                     // fp16 h mirror (dbl-buf)

// Sync state
struct alignas(128) BarSt { unsigned arrive; unsigned gen; unsigned pad[30]; };
__device__ BarSt g_bars[4];                                  // end-of-kernel fence
struct alignas(128) Cnt { unsigned v; unsigned pad[31]; };
__device__ Cnt g_cnt[4];                                     // per-step monotonic counter

__device__ __forceinline__ uint32_t pack_h2(float a, float b) {
    __half2 h = __floats2half2_rn(a, b);
    return *(uint32_t*)&h;
}

#define MMA_F16(acc, a0, a1, a2, a3, b0, b1)                                   \
    asm volatile(                                                              \
        "mma.sync.aligned.m16n8k16.row.col.f32.f16.f16.f32 "                   \
        "{%0,%1,%2,%3}, {%4,%5,%6,%7}, {%8,%9}, {%0,%1,%2,%3};\n"              \
        : "+f"((acc)[0]), "+f"((acc)[1]), "+f"((acc)[2]), "+f"((acc)[3])       \
        : "r"(a0), "r"(a1), "r"(a2), "r"(a3), "r"(b0), "r"(b1))

__device__ __forceinline__ void cp_async16(uint32_t dst, const void* src) {
    asm volatile("cp.async.cg.shared.global [%0], [%1], 16;" :: "r"(dst), "l"(src));
}
__device__ __forceinline__ unsigned ld_acq_gpu(unsigned* p) {
    unsigned v;
    asm volatile("ld.acquire.gpu.global.u32 %0, [%1];" : "=r"(v) : "l"(p) : "memory");
    return v;
}
__device__ __forceinline__ unsigned atom_add_rel_gpu(unsigned* p) {
    unsigned old;
    asm volatile("atom.add.release.gpu.global.u32 %0, [%1], 1;"
                 : "=r"(old) : "l"(p) : "memory");
    return old;
}

// ---------------------------------------------------------------------------
// Pre-convert W (1536 x 512 fp32) into fp16 MMA B-fragment order.
// ---------------------------------------------------------------------------
__global__ __launch_bounds__(256) void conv_wfrag_h(
    const float* __restrict__ W, uint32_t* __restrict__ F)
{
    int idx = blockIdx.x * 256 + threadIdx.x;
    int r    = idx & 1;
    int lane = (idx >> 1) & 31;
    int k16  = (idx >> 6) & 31;
    int nt   = idx >> 11;
    int n = nt * 8 + (lane >> 2);
    int k = k16 * 16 + (lane & 3) * 2 + r * 8;
    const float* p = W + (size_t)n * HID + k;
    F[idx] = pack_h2(p[0], p[1]);
}

// ---------------------------------------------------------------------------
// fp16 GEMM:  C[m,n] = sum_k A[m,k] * W[n,k] + bias[n]
// CTA tile 64x128; 8 warps; A staged pre-converted fp16 in SMEM.
// ---------------------------------------------------------------------------
#define APH 20

__global__ __launch_bounds__(256) void gemm_f16(
    const float* __restrict__ A, const uint32_t* __restrict__ Wf,
    const float* __restrict__ bias, float* __restrict__ C,
    int M, int N, int K)
{
    __shared__ uint32_t As[2][64][APH];

    const int bm  = blockIdx.y * 64;
    const int bnt = blockIdx.x * 16;
    const int tid = threadIdx.x;
    const int wid = tid >> 5;
    const int lane = tid & 31;
    const int wm = wid & 1;
    const int wn = wid >> 1;
    const int frow = lane >> 2;
    const int fk = lane & 3;

    float acc[2][4][4];
#pragma unroll
    for (int i = 0; i < 2; i++)
#pragma unroll
        for (int j = 0; j < 4; j++)
#pragma unroll
            for (int e = 0; e < 4; e++) acc[i][j][e] = 0.0f;

    const int lm = tid >> 2;
    const int lq = tid & 3;

    float4 pre[2];
    auto ldA = [&](int k0) {
#pragma unroll
        for (int it = 0; it < 2; it++) {
            int kq = lq * 2 + it;
            pre[it] = *(const float4*)(A + (size_t)(bm + lm) * K + k0 + kq * 4);
        }
    };
    auto stA = [&](int buf) {
#pragma unroll
        for (int it = 0; it < 2; it++) {
            int kq = lq * 2 + it;
            uint2 u = make_uint2(pack_h2(pre[it].x, pre[it].y),
                                 pack_h2(pre[it].z, pre[it].w));
            *(uint2*)&As[buf][lm][kq * 2] = u;
        }
    };

    ldA(0);
    stA(0);
    int buf = 0;

    for (int k0 = 0; k0 < K; k0 += 32) {
        __syncthreads();
        bool next = (k0 + 32 < K);
        if (next) ldA(k0 + 32);

#pragma unroll
        for (int sub = 0; sub < 2; sub++) {
            const int k16g = (k0 >> 4) + sub;
            uint32_t b0[4], b1[4];
#pragma unroll
            for (int j = 0; j < 4; j++) {
                size_t nt = (size_t)(bnt + wn * 4 + j);
                const uint2 v = __ldg((const uint2*)(Wf + ((nt * 32 + k16g) * 32 + lane) * 2));
                b0[j] = v.x; b1[j] = v.y;
            }
            uint32_t a[2][4];
#pragma unroll
            for (int i = 0; i < 2; i++) {
                int r0 = wm * 32 + i * 16 + frow;
                a[i][0] = As[buf][r0][sub * 8 + fk];
                a[i][1] = As[buf][r0 + 8][sub * 8 + fk];
                a[i][2] = As[buf][r0][sub * 8 + 4 + fk];
                a[i][3] = As[buf][r0 + 8][sub * 8 + 4 + fk];
            }
#pragma unroll
            for (int i = 0; i < 2; i++)
#pragma unroll
                for (int j = 0; j < 4; j++)
                    MMA_F16(acc[i][j], a[i][0], a[i][1], a[i][2], a[i][3],
                            b0[j], b1[j]);
        }
        if (next) stA(buf ^ 1);
        buf ^= 1;
    }

#pragma unroll
    for (int i = 0; i < 2; i++) {
        int mrow = bm + wm * 32 + i * 16 + frow;
#pragma unroll
        for (int j = 0; j < 4; j++) {
            int ncol = (bnt + wn * 4 + j) * 8 + fk * 2;
            float c0 = bias[ncol], c1 = bias[ncol + 1];
            *(float2*)(C + (size_t)mrow * N + ncol) =
                make_float2(acc[i][j][0] + c0, acc[i][j][1] + c1);
            *(float2*)(C + (size_t)(mrow + 8) * N + ncol) =
                make_float2(acc[i][j][2] + c0, acc[i][j][3] + c1);
        }
    }
}

// ---------------------------------------------------------------------------
// Gen-based barrier (used once at kernel end for counter reset)
// ---------------------------------------------------------------------------
__device__ __forceinline__ void group_barrier(int grp, unsigned nb)
{
    __syncthreads();
    if (threadIdx.x == 0) {
        unsigned gen0 = *(volatile unsigned*)&g_bars[grp].gen;
        unsigned prev = atom_add_rel_gpu(&g_bars[grp].arrive);
        if (prev == nb - 1) {
            *(volatile unsigned*)&g_bars[grp].arrive = 0;
            atom_add_rel_gpu(&g_bars[grp].gen);
        } else {
            while (ld_acq_gpu(&g_bars[grp].gen) == gen0) { }
        }
    }
    __syncthreads();
}

// ---------------------------------------------------------------------------
// Persistent recurrent kernel, fp16 MMA, register-carried h_prev,
// monotonic-counter barrier, fp16 mirror exchange.
// grid = 128 CTAs = 32 j-tiles x 4 b-groups, 256 threads.
// ---------------------------------------------------------------------------
#define HSH_PITCH 520          // halfs per row; conflict-free uint32 frag loads
#define PS_PITCH 50            // EVEN (float2-aligned); benign 2-way overlap
#define REC_SMEM_BYTES (16 * HSH_PITCH * 2 + 8 * 16 * PS_PITCH * 4)

__global__ __launch_bounds__(256, 1) void gru_layer_mma(
    const float* __restrict__ gx_all,  // (T, B, 3H)
    const float* __restrict__ h0,      // (B, H)
    const float* __restrict__ Whh,     // (3H, H)
    const float* __restrict__ bhh,     // (3H)
    float* __restrict__ out)           // (T, B, H)
{
    extern __shared__ float sm[];
    __half* h_sh = (__half*)sm;                       // [16][HSH_PITCH]
    float* Ps = sm + (16 * HSH_PITCH * 2) / 4;        // [8][16][PS_PITCH]

    const int jt = blockIdx.x & 31;
    const int bt = blockIdx.x >> 5;
    const int j0 = jt * 16;
    const int b0 = bt * 16;
    const int tid = threadIdx.x;
    const int w = tid >> 5;
    const int lane = tid & 31;

    // W_hh fp16 fragments into registers (once). Warp w owns k16-steps
    // [w*4, w*4+4).
    uint32_t wb0[6][4], wb1[6][4];
    {
        const int colq = lane >> 2;
        const int kq2 = (lane & 3) * 2;
#pragma unroll
        for (int tl = 0; tl < 6; tl++) {
            int g = tl >> 1;
            int col = j0 + (tl & 1) * 8 + colq;
            const float* wrow = Whh + (size_t)(g * HID + col) * HID;
#pragma unroll
            for (int kk = 0; kk < 4; kk++) {
                int ks = (w * 4 + kk) * 16 + kq2;
                wb0[tl][kk] = pack_h2(wrow[ks], wrow[ks + 1]);
                wb1[tl][kk] = pack_h2(wrow[ks + 8], wrow[ks + 9]);
            }
        }
    }

    const int gb = tid >> 4;
    const int gj = tid & 15;
    const int bg_g = b0 + gb;
    const int jg_g = j0 + gj;
    const float br_ = bhh[jg_g];
    const float bz_ = bhh[HID + jg_g];
    const float bn_ = bhh[2 * HID + jg_g];

    const int frow = lane >> 2;
    const int fk = lane & 3;

    // register-carried exact fp32 h_prev for this thread's (b, j)
    float hpv = __ldg(h0 + (size_t)bg_g * HID + jg_g);

    // prefetch t=0 input-side gates
    const float* gxp = gx_all + (size_t)bg_g * GATES;
    float xr = __ldg(gxp + jg_g);
    float xz = __ldg(gxp + HID + jg_g);
    float xn = __ldg(gxp + 2 * HID + jg_g);

    for (int t = 0; t < T_STEPS; t++) {
        if (t == 0) {
            // stage from fp32 h0 with conversion (same rounding as mirror)
#pragma unroll
            for (int q = 0; q < 8; q++) {
                int f = q * 256 + tid;
                int rr = f >> 7;
                int c4 = f & 127;
                float4 v = *((const float4*)(h0 + (size_t)(b0 + rr) * HID) + c4);
                uint2 u = make_uint2(pack_h2(v.x, v.y), pack_h2(v.z, v.w));
                *(uint2*)&h_sh[rr * HSH_PITCH + c4 * 4] = u;
            }
        } else {
            // stage fp16 mirror via cp.async (16 KB)
            const __half* mir = &g_hmir[(t - 1) & 1][b0][0];
#pragma unroll
            for (int q = 0; q < 4; q++) {
                int f = q * 256 + tid;
                int rr = f >> 6;
                int c = f & 63;
                uint32_t dst = (uint32_t)__cvta_generic_to_shared(
                    &h_sh[rr * HSH_PITCH + c * 8]);
                cp_async16(dst, mir + (size_t)rr * HID + c * 8);
            }
            asm volatile("cp.async.commit_group;");
            asm volatile("cp.async.wait_group 0;");
        }
        __syncthreads();

        // MMA over this warp's k-slice: 4 k16-steps x 6 n-tiles
        float acc[6][4];
#pragma unroll
        for (int tl = 0; tl < 6; tl++) {
            acc[tl][0] = 0.f; acc[tl][1] = 0.f; acc[tl][2] = 0.f; acc[tl][3] = 0.f;
        }
#pragma unroll
        for (int kk = 0; kk < 4; kk++) {
            int kbase = (w * 4 + kk) * 16;
            uint32_t a0 = *(const uint32_t*)&h_sh[frow * HSH_PITCH + kbase + fk * 2];
            uint32_t a1 = *(const uint32_t*)&h_sh[(frow + 8) * HSH_PITCH + kbase + fk * 2];
            uint32_t a2 = *(const uint32_t*)&h_sh[frow * HSH_PITCH + kbase + 8 + fk * 2];
            uint32_t a3 = *(const uint32_t*)&h_sh[(frow + 8) * HSH_PITCH + kbase + 8 + fk * 2];
#pragma unroll
            for (int tl = 0; tl < 6; tl++)
                MMA_F16(acc[tl], a0, a1, a2, a3, wb0[tl][kk], wb1[tl][kk]);
        }
        {
            int m = lane >> 2;
            int ncb = 2 * (lane & 3);
#pragma unroll
            for (int tl = 0; tl < 6; tl++) {
                *(float2*)&Ps[(w * 16 + m) * PS_PITCH + tl * 8 + ncb] =
                    make_float2(acc[tl][0], acc[tl][1]);
                *(float2*)&Ps[(w * 16 + m + 8) * PS_PITCH + tl * 8 + ncb] =
                    make_float2(acc[tl][2], acc[tl][3]);
            }
        }
        __syncthreads();

        // reduce 8 partials + gating
        float hr = 0.f, hz = 0.f, hn = 0.f;
#pragma unroll
        for (int ww = 0; ww < 8; ww++) {
            const float* p = &Ps[(ww * 16 + gb) * PS_PITCH];
            hr += p[gj];
            hz += p[16 + gj];
            hn += p[32 + gj];
        }
        float r = 1.0f / (1.0f + __expf(-(xr + hr + br_)));
        float z = 1.0f / (1.0f + __expf(-(xz + hz + bz_)));
        float n = tanhf(xn + r * (hn + bn_));
        float hnew = (1.0f - z) * n + z * hpv;
        hpv = hnew;   // register-carried h_prev for next step

        // mirror write must be visible before the release; out is pure output
        g_hmir[t & 1][bg_g][jg_g] = __float2half_rn(hnew);
        out[(size_t)t * BATCH * HID + (size_t)bg_g * HID + jg_g] = hnew;

        // prefetch next step's input-side gates (overlaps barrier wait)
        int tn = (t + 1 < T_STEPS) ? t + 1 : t;
        const float* gxn = gx_all + (size_t)tn * BATCH * GATES + (size_t)bg_g * GATES;
        xr = __ldg(gxn + jg_g);
        xz = __ldg(gxn + HID + jg_g);
        xn = __ldg(gxn + 2 * HID + jg_g);

        if (t != T_STEPS - 1) {
            // monotonic-counter barrier: one release-add; pollers watch the
            // same line reach 32*(t+1) -- single propagation hop
            __syncthreads();
            if (tid == 0) {
                atom_add_rel_gpu(&g_cnt[bt].v);
                unsigned target = 32u * (unsigned)(t + 1);
                while (ld_acq_gpu(&g_cnt[bt].v) < target) { }
            }
            __syncthreads();
        }
    }

    // end: fence all CTAs, then reset the step counter for the next replay
    group_barrier(bt, 32);
    if (jt == 0 && tid == 0) *(volatile unsigned*)&g_cnt[bt].v = 0;
}

// ---------------------------------------------------------------------------
extern "C" void kernel_launch(void* const* d_in, const int* in_sizes, int n_in,
                              void* d_out, int out_size)
{
    const float* x    = (const float*)d_in[0];
    const float* h0   = (const float*)d_in[1];
    const float* w_ih = (const float*)d_in[2];
    const float* w_hh = (const float*)d_in[3];
    const float* b_ih = (const float*)d_in[4];
    const float* b_hh = (const float*)d_in[5];
    float* out_final  = (float*)d_out;

    float* gates; float* buf1; uint32_t* wfrag;
    cudaGetSymbolAddress((void**)&gates, g_gates);
    cudaGetSymbolAddress((void**)&buf1, g_buf1);
    cudaGetSymbolAddress((void**)&wfrag, g_wfrag);

    static int smem_configured = 0;
    if (!smem_configured) {
        cudaFuncSetAttribute(gru_layer_mma,
                             cudaFuncAttributeMaxDynamicSharedMemorySize, REC_SMEM_BYTES);
        smem_configured = 1;
    }

    const int M = T_STEPS * BATCH;
    const int K = HID;

    for (int l = 0; l < NLAYERS; l++) {
        const float* inp   = (l == 0) ? x : buf1;
        float*       out   = (l == NLAYERS - 1) ? out_final : buf1;
        const float* wih_l = w_ih + (size_t)l * GATES * HID;
        const float* whh_l = w_hh + (size_t)l * GATES * HID;
        const float* bih_l = b_ih + (size_t)l * GATES;
        const float* bhh_l = b_hh + (size_t)l * GATES;
        const float* h0_l  = h0 + (size_t)l * BATCH * HID;

        conv_wfrag_h<<<1536, 256>>>(wih_l, wfrag);

        dim3 ggrid(GATES / 128, M / 64);
        gemm_f16<<<ggrid, 256>>>(inp, wfrag, bih_l, gates, M, GATES, K);

        gru_layer_mma<<<128, 256, REC_SMEM_BYTES>>>(gates, h0_l, whh_l, bhh_l, out);
    }
}

// round 13
// speedup vs baseline: 1.7479x; 1.1908x over previous
#include <cuda_runtime.h>
#include <cuda_fp16.h>
#include <cstdint>

// Problem constants
#define T_STEPS 512
#define BATCH   64
#define HID     512
#define GATES   1536   // 3*HID
#define NLAYERS 2

// Scratch (device globals; no allocation)
__device__ float g_gates[(size_t)T_STEPS * BATCH * GATES];   // input gates
__device__ float g_buf1[(size_t)T_STEPS * BATCH * HID];      // layer-1 output
__device__ uint32_t g_wfrag[(size_t)192 * 32 * 32 * 2];      // frag-ordered fp16 W_ih
__device__ __half g_hmir[2][BATCH][HID];                     // fp16 h mirror (dbl-buf)

// Sync state
struct alignas(128) BarSt { unsigned arrive; unsigned gen; unsigned pad[30]; };
__device__ BarSt g_bars[4];                                  // end-of-kernel fence
struct alignas(128) Cnt { unsigned v; unsigned pad[31]; };
__device__ Cnt g_cnt2[4][8];   // [b-group][j-octile] monotonic producer counters

__device__ __forceinline__ uint32_t pack_h2(float a, float b) {
    __half2 h = __floats2half2_rn(a, b);
    return *(uint32_t*)&h;
}

#define MMA_F16(acc, a0, a1, a2, a3, b0, b1)                                   \
    asm volatile(                                                              \
        "mma.sync.aligned.m16n8k16.row.col.f32.f16.f16.f32 "                   \
        "{%0,%1,%2,%3}, {%4,%5,%6,%7}, {%8,%9}, {%0,%1,%2,%3};\n"              \
        : "+f"((acc)[0]), "+f"((acc)[1]), "+f"((acc)[2]), "+f"((acc)[3])       \
        : "r"(a0), "r"(a1), "r"(a2), "r"(a3), "r"(b0), "r"(b1))

__device__ __forceinline__ void cp_async16(uint32_t dst, const void* src) {
    asm volatile("cp.async.cg.shared.global [%0], [%1], 16;" :: "r"(dst), "l"(src));
}
__device__ __forceinline__ unsigned ld_acq_gpu(unsigned* p) {
    unsigned v;
    asm volatile("ld.acquire.gpu.global.u32 %0, [%1];" : "=r"(v) : "l"(p) : "memory");
    return v;
}
__device__ __forceinline__ void red_add_rel_gpu(unsigned* p) {
    asm volatile("red.release.gpu.global.add.u32 [%0], 1;" :: "l"(p) : "memory");
}
__device__ __forceinline__ unsigned atom_add_rel_gpu(unsigned* p) {
    unsigned old;
    asm volatile("atom.add.release.gpu.global.u32 %0, [%1], 1;"
                 : "=r"(old) : "l"(p) : "memory");
    return old;
}

// ---------------------------------------------------------------------------
// Pre-convert W (1536 x 512 fp32) into fp16 MMA B-fragment order.
// ---------------------------------------------------------------------------
__global__ __launch_bounds__(256) void conv_wfrag_h(
    const float* __restrict__ W, uint32_t* __restrict__ F)
{
    int idx = blockIdx.x * 256 + threadIdx.x;
    int r    = idx & 1;
    int lane = (idx >> 1) & 31;
    int k16  = (idx >> 6) & 31;
    int nt   = idx >> 11;
    int n = nt * 8 + (lane >> 2);
    int k = k16 * 16 + (lane & 3) * 2 + r * 8;
    const float* p = W + (size_t)n * HID + k;
    F[idx] = pack_h2(p[0], p[1]);
}

// ---------------------------------------------------------------------------
// fp16 GEMM:  C[m,n] = sum_k A[m,k] * W[n,k] + bias[n]
// CTA tile 64x128; 8 warps; A staged pre-converted fp16 in SMEM.
// ---------------------------------------------------------------------------
#define APH 20

__global__ __launch_bounds__(256) void gemm_f16(
    const float* __restrict__ A, const uint32_t* __restrict__ Wf,
    const float* __restrict__ bias, float* __restrict__ C,
    int M, int N, int K)
{
    __shared__ uint32_t As[2][64][APH];

    const int bm  = blockIdx.y * 64;
    const int bnt = blockIdx.x * 16;
    const int tid = threadIdx.x;
    const int wid = tid >> 5;
    const int lane = tid & 31;
    const int wm = wid & 1;
    const int wn = wid >> 1;
    const int frow = lane >> 2;
    const int fk = lane & 3;

    float acc[2][4][4];
#pragma unroll
    for (int i = 0; i < 2; i++)
#pragma unroll
        for (int j = 0; j < 4; j++)
#pragma unroll
            for (int e = 0; e < 4; e++) acc[i][j][e] = 0.0f;

    const int lm = tid >> 2;
    const int lq = tid & 3;

    float4 pre[2];
    auto ldA = [&](int k0) {
#pragma unroll
        for (int it = 0; it < 2; it++) {
            int kq = lq * 2 + it;
            pre[it] = *(const float4*)(A + (size_t)(bm + lm) * K + k0 + kq * 4);
        }
    };
    auto stA = [&](int buf) {
#pragma unroll
        for (int it = 0; it < 2; it++) {
            int kq = lq * 2 + it;
            uint2 u = make_uint2(pack_h2(pre[it].x, pre[it].y),
                                 pack_h2(pre[it].z, pre[it].w));
            *(uint2*)&As[buf][lm][kq * 2] = u;
        }
    };

    ldA(0);
    stA(0);
    int buf = 0;

    for (int k0 = 0; k0 < K; k0 += 32) {
        __syncthreads();
        bool next = (k0 + 32 < K);
        if (next) ldA(k0 + 32);

#pragma unroll
        for (int sub = 0; sub < 2; sub++) {
            const int k16g = (k0 >> 4) + sub;
            uint32_t b0[4], b1[4];
#pragma unroll
            for (int j = 0; j < 4; j++) {
                size_t nt = (size_t)(bnt + wn * 4 + j);
                const uint2 v = __ldg((const uint2*)(Wf + ((nt * 32 + k16g) * 32 + lane) * 2));
                b0[j] = v.x; b1[j] = v.y;
            }
            uint32_t a[2][4];
#pragma unroll
            for (int i = 0; i < 2; i++) {
                int r0 = wm * 32 + i * 16 + frow;
                a[i][0] = As[buf][r0][sub * 8 + fk];
                a[i][1] = As[buf][r0 + 8][sub * 8 + fk];
                a[i][2] = As[buf][r0][sub * 8 + 4 + fk];
                a[i][3] = As[buf][r0 + 8][sub * 8 + 4 + fk];
            }
#pragma unroll
            for (int i = 0; i < 2; i++)
#pragma unroll
                for (int j = 0; j < 4; j++)
                    MMA_F16(acc[i][j], a[i][0], a[i][1], a[i][2], a[i][3],
                            b0[j], b1[j]);
        }
        if (next) stA(buf ^ 1);
        buf ^= 1;
    }

#pragma unroll
    for (int i = 0; i < 2; i++) {
        int mrow = bm + wm * 32 + i * 16 + frow;
#pragma unroll
        for (int j = 0; j < 4; j++) {
            int ncol = (bnt + wn * 4 + j) * 8 + fk * 2;
            float c0 = bias[ncol], c1 = bias[ncol + 1];
            *(float2*)(C + (size_t)mrow * N + ncol) =
                make_float2(acc[i][j][0] + c0, acc[i][j][1] + c1);
            *(float2*)(C + (size_t)(mrow + 8) * N + ncol) =
                make_float2(acc[i][j][2] + c0, acc[i][j][3] + c1);
        }
    }
}

// ---------------------------------------------------------------------------
// Gen-based barrier (used once at kernel end for counter reset)
// ---------------------------------------------------------------------------
__device__ __forceinline__ void group_barrier(int grp, unsigned nb)
{
    __syncthreads();
    if (threadIdx.x == 0) {
        unsigned gen0 = *(volatile unsigned*)&g_bars[grp].gen;
        unsigned prev = atom_add_rel_gpu(&g_bars[grp].arrive);
        if (prev == nb - 1) {
            *(volatile unsigned*)&g_bars[grp].arrive = 0;
            atom_add_rel_gpu(&g_bars[grp].gen);
        } else {
            while (ld_acq_gpu(&g_bars[grp].gen) == gen0) { }
        }
    }
    __syncthreads();
}

// ---------------------------------------------------------------------------
// Persistent recurrent kernel, fp16 MMA, register-carried h_prev,
// PIPELINED per-octile producer counters: warp w consumes h-slice
// k in [w*64, w*64+64) produced by CTAs jt in [4w, 4w+4); it waits only
// on that octile's counter, stages its own 2 KB, and MMAs immediately.
// grid = 128 CTAs = 32 j-tiles x 4 b-groups, 256 threads.
// ---------------------------------------------------------------------------
#define HSH_PITCH 520          // halfs per row; conflict-free uint32 frag loads
#define PS_PITCH 50            // even (float2-aligned)
#define REC_SMEM_BYTES (16 * HSH_PITCH * 2 + 8 * 16 * PS_PITCH * 4)

__global__ __launch_bounds__(256, 1) void gru_layer_mma(
    const float* __restrict__ gx_all,  // (T, B, 3H)
    const float* __restrict__ h0,      // (B, H)
    const float* __restrict__ Whh,     // (3H, H)
    const float* __restrict__ bhh,     // (3H)
    float* __restrict__ out)           // (T, B, H)
{
    extern __shared__ float sm[];
    __half* h_sh = (__half*)sm;                       // [16][HSH_PITCH]
    float* Ps = sm + (16 * HSH_PITCH * 2) / 4;        // [8][16][PS_PITCH]

    const int jt = blockIdx.x & 31;
    const int bt = blockIdx.x >> 5;
    const int j0 = jt * 16;
    const int b0 = bt * 16;
    const int tid = threadIdx.x;
    const int w = tid >> 5;
    const int lane = tid & 31;
    const int my_oct = jt >> 2;        // octile this CTA produces into

    // W_hh fp16 fragments into registers (once). Warp w owns k16-steps
    // [w*4, w*4+4)  (= k in [w*64, w*64+64)).
    uint32_t wb0[6][4], wb1[6][4];
    {
        const int colq = lane >> 2;
        const int kq2 = (lane & 3) * 2;
#pragma unroll
        for (int tl = 0; tl < 6; tl++) {
            int g = tl >> 1;
            int col = j0 + (tl & 1) * 8 + colq;
            const float* wrow = Whh + (size_t)(g * HID + col) * HID;
#pragma unroll
            for (int kk = 0; kk < 4; kk++) {
                int ks = (w * 4 + kk) * 16 + kq2;
                wb0[tl][kk] = pack_h2(wrow[ks], wrow[ks + 1]);
                wb1[tl][kk] = pack_h2(wrow[ks + 8], wrow[ks + 9]);
            }
        }
    }

    const int gb = tid >> 4;
    const int gj = tid & 15;
    const int bg_g = b0 + gb;
    const int jg_g = j0 + gj;
    const float br_ = bhh[jg_g];
    const float bz_ = bhh[HID + jg_g];
    const float bn_ = bhh[2 * HID + jg_g];

    const int frow = lane >> 2;
    const int fk = lane & 3;

    // register-carried exact fp32 h_prev for this thread's (b, j)
    float hpv = __ldg(h0 + (size_t)bg_g * HID + jg_g);

    // prefetch t=0 input-side gates
    const float* gxp = gx_all + (size_t)bg_g * GATES;
    float xr = __ldg(gxp + jg_g);
    float xz = __ldg(gxp + HID + jg_g);
    float xn = __ldg(gxp + 2 * HID + jg_g);

    for (int t = 0; t < T_STEPS; t++) {
        if (t == 0) {
            // warp stages its OWN k-slice from fp32 h0 (16 rows x 64 floats)
#pragma unroll
            for (int it = 0; it < 8; it++) {
                int f = it * 32 + lane;      // 0..255
                int rr = f >> 4;             // 0..15
                int c4 = f & 15;             // float4 within 64 floats
                float4 v = *((const float4*)(h0 + (size_t)(b0 + rr) * HID + w * 64) + c4);
                uint2 u = make_uint2(pack_h2(v.x, v.y), pack_h2(v.z, v.w));
                *(uint2*)&h_sh[rr * HSH_PITCH + w * 64 + c4 * 4] = u;
            }
        } else {
            // wait ONLY for this warp's 4 producer CTAs, then stage 2 KB
            unsigned target = 4u * (unsigned)t;
            unsigned* cp = &g_cnt2[bt][w].v;
            while (ld_acq_gpu(cp) < target) { }

            const __half* mir = &g_hmir[(t - 1) & 1][b0][0];
#pragma unroll
            for (int it = 0; it < 4; it++) {
                int f = it * 32 + lane;      // 0..127
                int rr = f >> 3;             // 0..15
                int c  = f & 7;              // 16B chunk within 128B row-slice
                uint32_t dst = (uint32_t)__cvta_generic_to_shared(
                    &h_sh[rr * HSH_PITCH + w * 64 + c * 8]);
                cp_async16(dst, mir + (size_t)rr * HID + w * 64 + c * 8);
            }
            asm volatile("cp.async.commit_group;");
            asm volatile("cp.async.wait_group 0;");
        }
        // NO CTA sync: each warp consumes only the slice it staged.

        // MMA over this warp's k-slice: 4 k16-steps x 6 n-tiles
        float acc[6][4];
#pragma unroll
        for (int tl = 0; tl < 6; tl++) {
            acc[tl][0] = 0.f; acc[tl][1] = 0.f; acc[tl][2] = 0.f; acc[tl][3] = 0.f;
        }
#pragma unroll
        for (int kk = 0; kk < 4; kk++) {
            int kbase = (w * 4 + kk) * 16;
            uint32_t a0 = *(const uint32_t*)&h_sh[frow * HSH_PITCH + kbase + fk * 2];
            uint32_t a1 = *(const uint32_t*)&h_sh[(frow + 8) * HSH_PITCH + kbase + fk * 2];
            uint32_t a2 = *(const uint32_t*)&h_sh[frow * HSH_PITCH + kbase + 8 + fk * 2];
            uint32_t a3 = *(const uint32_t*)&h_sh[(frow + 8) * HSH_PITCH + kbase + 8 + fk * 2];
#pragma unroll
            for (int tl = 0; tl < 6; tl++)
                MMA_F16(acc[tl], a0, a1, a2, a3, wb0[tl][kk], wb1[tl][kk]);
        }
        {
            int m = lane >> 2;
            int ncb = 2 * (lane & 3);
#pragma unroll
            for (int tl = 0; tl < 6; tl++) {
                *(float2*)&Ps[(w * 16 + m) * PS_PITCH + tl * 8 + ncb] =
                    make_float2(acc[tl][0], acc[tl][1]);
                *(float2*)&Ps[(w * 16 + m + 8) * PS_PITCH + tl * 8 + ncb] =
                    make_float2(acc[tl][2], acc[tl][3]);
            }
        }
        __syncthreads();   // all warps' partials visible

        // reduce 8 partials + gating
        float hr = 0.f, hz = 0.f, hn = 0.f;
#pragma unroll
        for (int ww = 0; ww < 8; ww++) {
            const float* p = &Ps[(ww * 16 + gb) * PS_PITCH];
            hr += p[gj];
            hz += p[16 + gj];
            hn += p[32 + gj];
        }
        float r = 1.0f / (1.0f + __expf(-(xr + hr + br_)));
        float z = 1.0f / (1.0f + __expf(-(xz + hz + bz_)));
        float n = tanhf(xn + r * (hn + bn_));
        float hnew = (1.0f - z) * n + z * hpv;
        hpv = hnew;

        // publish fp16 mirror, then release-arrive on this CTA's octile
        g_hmir[t & 1][bg_g][jg_g] = __float2half_rn(hnew);
        __syncthreads();   // mirror writes of all threads precede the release
        if (tid == 0 && t != T_STEPS - 1)
            red_add_rel_gpu(&g_cnt2[bt][my_oct].v);

        // pure output + next-step gx prefetch (overlap producers' propagation)
        out[(size_t)t * BATCH * HID + (size_t)bg_g * HID + jg_g] = hnew;
        int tn = (t + 1 < T_STEPS) ? t + 1 : t;
        const float* gxn = gx_all + (size_t)tn * BATCH * GATES + (size_t)bg_g * GATES;
        xr = __ldg(gxn + jg_g);
        xz = __ldg(gxn + HID + jg_g);
        xn = __ldg(gxn + 2 * HID + jg_g);
    }

    // end: fence all CTAs of the group, then reset this group's counters
    group_barrier(bt, 32);
    if (jt == 0 && tid < 8) *(volatile unsigned*)&g_cnt2[bt][tid].v = 0;
}

// ---------------------------------------------------------------------------
extern "C" void kernel_launch(void* const* d_in, const int* in_sizes, int n_in,
                              void* d_out, int out_size)
{
    const float* x    = (const float*)d_in[0];
    const float* h0   = (const float*)d_in[1];
    const float* w_ih = (const float*)d_in[2];
    const float* w_hh = (const float*)d_in[3];
    const float* b_ih = (const float*)d_in[4];
    const float* b_hh = (const float*)d_in[5];
    float* out_final  = (float*)d_out;

    float* gates; float* buf1; uint32_t* wfrag;
    cudaGetSymbolAddress((void**)&gates, g_gates);
    cudaGetSymbolAddress((void**)&buf1, g_buf1);
    cudaGetSymbolAddress((void**)&wfrag, g_wfrag);

    static int smem_configured = 0;
    if (!smem_configured) {
        cudaFuncSetAttribute(gru_layer_mma,
                             cudaFuncAttributeMaxDynamicSharedMemorySize, REC_SMEM_BYTES);
        smem_configured = 1;
    }

    const int M = T_STEPS * BATCH;
    const int K = HID;

    for (int l = 0; l < NLAYERS; l++) {
        const float* inp   = (l == 0) ? x : buf1;
        float*       out   = (l == NLAYERS - 1) ? out_final : buf1;
        const float* wih_l = w_ih + (size_t)l * GATES * HID;
        const float* whh_l = w_hh + (size_t)l * GATES * HID;
        const float* bih_l = b_ih + (size_t)l * GATES;
        const float* bhh_l = b_hh + (size_t)l * GATES;
        const float* h0_l  = h0 + (size_t)l * BATCH * HID;

        conv_wfrag_h<<<1536, 256>>>(wih_l, wfrag);

        dim3 ggrid(GATES / 128, M / 64);
        gemm_f16<<<ggrid, 256>>>(inp, wfrag, bih_l, gates, M, GATES, K);

        gru_layer_mma<<<128, 256, REC_SMEM_BYTES>>>(gates, h0_l, whh_l, bhh_l, out);
    }
}

// round 14
// speedup vs baseline: 1.9614x; 1.1221x over previous
#include <cuda_runtime.h>
#include <cuda_fp16.h>
#include <cstdint>

// Problem constants
#define T_STEPS 512
#define BATCH   64
#define HID     512
#define GATES   1536   // 3*HID
#define NLAYERS 2

// Scratch (device globals; no allocation)
__device__ float g_gates[(size_t)T_STEPS * BATCH * GATES];   // layer-1 input gates
__device__ uint32_t g_wfrag[(size_t)192 * 32 * 32 * 2];      // frag-ordered fp16 W_ih1
__device__ __half g_hmir1[2][BATCH][HID];                    // fp16 h1 mirror (dbl-buf)
__device__ __half g_hmir2[2][BATCH][HID];                    // fp16 h2 mirror (dbl-buf)

// Sync state
struct alignas(128) BarSt { unsigned arrive; unsigned gen; unsigned pad[30]; };
__device__ BarSt g_bars[4];                                  // end-of-kernel fence
struct alignas(128) Cnt { unsigned v; unsigned pad[31]; };
__device__ Cnt g_cntL[2][4][8];   // [layer][b-group][j-octile] producer counters

__device__ __forceinline__ uint32_t pack_h2(float a, float b) {
    __half2 h = __floats2half2_rn(a, b);
    return *(uint32_t*)&h;
}

#define MMA_F16(acc, a0, a1, a2, a3, b0, b1)                                   \
    asm volatile(                                                              \
        "mma.sync.aligned.m16n8k16.row.col.f32.f16.f16.f32 "                   \
        "{%0,%1,%2,%3}, {%4,%5,%6,%7}, {%8,%9}, {%0,%1,%2,%3};\n"              \
        : "+f"((acc)[0]), "+f"((acc)[1]), "+f"((acc)[2]), "+f"((acc)[3])       \
        : "r"(a0), "r"(a1), "r"(a2), "r"(a3), "r"(b0), "r"(b1))

__device__ __forceinline__ void cp_async16(uint32_t dst, const void* src) {
    asm volatile("cp.async.cg.shared.global [%0], [%1], 16;" :: "r"(dst), "l"(src));
}
__device__ __forceinline__ unsigned ld_acq_gpu(unsigned* p) {
    unsigned v;
    asm volatile("ld.acquire.gpu.global.u32 %0, [%1];" : "=r"(v) : "l"(p) : "memory");
    return v;
}
__device__ __forceinline__ void red_add_rel_gpu(unsigned* p) {
    asm volatile("red.release.gpu.global.add.u32 [%0], 1;" :: "l"(p) : "memory");
}
__device__ __forceinline__ unsigned atom_add_rel_gpu(unsigned* p) {
    unsigned old;
    asm volatile("atom.add.release.gpu.global.u32 %0, [%1], 1;"
                 : "=r"(old) : "l"(p) : "memory");
    return old;
}

// ---------------------------------------------------------------------------
// Pre-convert W (1536 x 512 fp32) into fp16 MMA B-fragment order (layer 1).
// ---------------------------------------------------------------------------
__global__ __launch_bounds__(256) void conv_wfrag_h(
    const float* __restrict__ W, uint32_t* __restrict__ F)
{
    int idx = blockIdx.x * 256 + threadIdx.x;
    int r    = idx & 1;
    int lane = (idx >> 1) & 31;
    int k16  = (idx >> 6) & 31;
    int nt   = idx >> 11;
    int n = nt * 8 + (lane >> 2);
    int k = k16 * 16 + (lane & 3) * 2 + r * 8;
    const float* p = W + (size_t)n * HID + k;
    F[idx] = pack_h2(p[0], p[1]);
}

// ---------------------------------------------------------------------------
// fp16 GEMM for layer-1 input projection (unchanged from R13).
// ---------------------------------------------------------------------------
#define APH 20

__global__ __launch_bounds__(256) void gemm_f16(
    const float* __restrict__ A, const uint32_t* __restrict__ Wf,
    const float* __restrict__ bias, float* __restrict__ C,
    int M, int N, int K)
{
    __shared__ uint32_t As[2][64][APH];

    const int bm  = blockIdx.y * 64;
    const int bnt = blockIdx.x * 16;
    const int tid = threadIdx.x;
    const int wid = tid >> 5;
    const int lane = tid & 31;
    const int wm = wid & 1;
    const int wn = wid >> 1;
    const int frow = lane >> 2;
    const int fk = lane & 3;

    float acc[2][4][4];
#pragma unroll
    for (int i = 0; i < 2; i++)
#pragma unroll
        for (int j = 0; j < 4; j++)
#pragma unroll
            for (int e = 0; e < 4; e++) acc[i][j][e] = 0.0f;

    const int lm = tid >> 2;
    const int lq = tid & 3;

    float4 pre[2];
    auto ldA = [&](int k0) {
#pragma unroll
        for (int it = 0; it < 2; it++) {
            int kq = lq * 2 + it;
            pre[it] = *(const float4*)(A + (size_t)(bm + lm) * K + k0 + kq * 4);
        }
    };
    auto stA = [&](int buf) {
#pragma unroll
        for (int it = 0; it < 2; it++) {
            int kq = lq * 2 + it;
            uint2 u = make_uint2(pack_h2(pre[it].x, pre[it].y),
                                 pack_h2(pre[it].z, pre[it].w));
            *(uint2*)&As[buf][lm][kq * 2] = u;
        }
    };

    ldA(0);
    stA(0);
    int buf = 0;

    for (int k0 = 0; k0 < K; k0 += 32) {
        __syncthreads();
        bool next = (k0 + 32 < K);
        if (next) ldA(k0 + 32);

#pragma unroll
        for (int sub = 0; sub < 2; sub++) {
            const int k16g = (k0 >> 4) + sub;
            uint32_t b0[4], b1[4];
#pragma unroll
            for (int j = 0; j < 4; j++) {
                size_t nt = (size_t)(bnt + wn * 4 + j);
                const uint2 v = __ldg((const uint2*)(Wf + ((nt * 32 + k16g) * 32 + lane) * 2));
                b0[j] = v.x; b1[j] = v.y;
            }
            uint32_t a[2][4];
#pragma unroll
            for (int i = 0; i < 2; i++) {
                int r0 = wm * 32 + i * 16 + frow;
                a[i][0] = As[buf][r0][sub * 8 + fk];
                a[i][1] = As[buf][r0 + 8][sub * 8 + fk];
                a[i][2] = As[buf][r0][sub * 8 + 4 + fk];
                a[i][3] = As[buf][r0 + 8][sub * 8 + 4 + fk];
            }
#pragma unroll
            for (int i = 0; i < 2; i++)
#pragma unroll
                for (int j = 0; j < 4; j++)
                    MMA_F16(acc[i][j], a[i][0], a[i][1], a[i][2], a[i][3],
                            b0[j], b1[j]);
        }
        if (next) stA(buf ^ 1);
        buf ^= 1;
    }

#pragma unroll
    for (int i = 0; i < 2; i++) {
        int mrow = bm + wm * 32 + i * 16 + frow;
#pragma unroll
        for (int j = 0; j < 4; j++) {
            int ncol = (bnt + wn * 4 + j) * 8 + fk * 2;
            float c0 = bias[ncol], c1 = bias[ncol + 1];
            *(float2*)(C + (size_t)mrow * N + ncol) =
                make_float2(acc[i][j][0] + c0, acc[i][j][1] + c1);
            *(float2*)(C + (size_t)(mrow + 8) * N + ncol) =
                make_float2(acc[i][j][2] + c0, acc[i][j][3] + c1);
        }
    }
}

// ---------------------------------------------------------------------------
// Gen-based barrier (used once at kernel end for counter reset)
// ---------------------------------------------------------------------------
__device__ __forceinline__ void group_barrier(int grp, unsigned nb)
{
    __syncthreads();
    if (threadIdx.x == 0) {
        unsigned gen0 = *(volatile unsigned*)&g_bars[grp].gen;
        unsigned prev = atom_add_rel_gpu(&g_bars[grp].arrive);
        if (prev == nb - 1) {
            *(volatile unsigned*)&g_bars[grp].arrive = 0;
            atom_add_rel_gpu(&g_bars[grp].gen);
        } else {
            while (ld_acq_gpu(&g_bars[grp].gen) == gen0) { }
        }
    }
    __syncthreads();
}

// ---------------------------------------------------------------------------
// Fused 2-layer persistent kernel with 1-step software pipeline skew.
// Iteration t: layer-1 step t (t<512), then layer-2 step t-1 (t>=1).
// 128 CTAs = 32 j-tiles x 4 b-groups, 256 threads, per-octile counters/layer.
// ---------------------------------------------------------------------------
#define HSH_PITCH 520
#define PS_PITCH 50
// SMEM layout (bytes): W2i frags 49152 | W2h frags 49152 | Ps_a 25600 |
//                      Ps_b 25600 | h1 16640 | h2 16640   = 182784
#define W2_ENTRIES (6 * 32 * 32)
#define SM_W2I 0
#define SM_W2H (W2_ENTRIES * 8)
#define SM_PSA (2 * W2_ENTRIES * 8)
#define SM_PSB (SM_PSA + 8 * 16 * PS_PITCH * 4)
#define SM_H1  (SM_PSB + 8 * 16 * PS_PITCH * 4)
#define SM_H2  (SM_H1 + 16 * HSH_PITCH * 2)
#define FUSED_SMEM_BYTES (SM_H2 + 16 * HSH_PITCH * 2)

__global__ __launch_bounds__(256, 1) void gru_fused2(
    const float* __restrict__ gx1_all,  // (T, B, 3H) layer-1 input gates
    const float* __restrict__ h0,       // (L, B, H)
    const float* __restrict__ Whh1,     // (3H, H)
    const float* __restrict__ bhh1,     // (3H)
    const float* __restrict__ Wih2,     // (3H, H)
    const float* __restrict__ bih2,     // (3H)
    const float* __restrict__ Whh2,     // (3H, H)
    const float* __restrict__ bhh2,     // (3H)
    float* __restrict__ out)            // (T, B, H) layer-2 output
{
    extern __shared__ char smc[];
    uint2*  W2i  = (uint2*)(smc + SM_W2I);
    uint2*  W2h  = (uint2*)(smc + SM_W2H);
    float*  Ps_a = (float*)(smc + SM_PSA);
    float*  Ps_b = (float*)(smc + SM_PSB);
    __half* h1_s = (__half*)(smc + SM_H1);
    __half* h2_s = (__half*)(smc + SM_H2);

    const int jt = blockIdx.x & 31;
    const int bt = blockIdx.x >> 5;
    const int j0 = jt * 16;
    const int b0 = bt * 16;
    const int tid = threadIdx.x;
    const int w = tid >> 5;
    const int lane = tid & 31;
    const int my_oct = jt >> 2;

    const float* h0_l1 = h0;
    const float* h0_l2 = h0 + (size_t)BATCH * HID;

    // ---- one-time: W_hh1 frags -> registers; W_ih2/W_hh2 frags -> SMEM
    uint32_t wb0[6][4], wb1[6][4];
    {
        const int colq = lane >> 2;
        const int kq2 = (lane & 3) * 2;
#pragma unroll
        for (int tl = 0; tl < 6; tl++) {
            int g = tl >> 1;
            int col = j0 + (tl & 1) * 8 + colq;
            const float* wrow = Whh1 + (size_t)(g * HID + col) * HID;
#pragma unroll
            for (int kk = 0; kk < 4; kk++) {
                int ks = (w * 4 + kk) * 16 + kq2;
                wb0[tl][kk] = pack_h2(wrow[ks], wrow[ks + 1]);
                wb1[tl][kk] = pack_h2(wrow[ks + 8], wrow[ks + 9]);
            }
        }
    }
    for (int i = tid; i < W2_ENTRIES; i += 256) {
        int lane_ = i & 31;
        int k16_ = (i >> 5) & 31;
        int tl_ = i >> 10;
        int g = tl_ >> 1;
        int col = j0 + (tl_ & 1) * 8 + (lane_ >> 2);
        int k = k16_ * 16 + (lane_ & 3) * 2;
        const float* wi = Wih2 + (size_t)(g * HID + col) * HID;
        const float* wh = Whh2 + (size_t)(g * HID + col) * HID;
        W2i[i] = make_uint2(pack_h2(wi[k], wi[k + 1]), pack_h2(wi[k + 8], wi[k + 9]));
        W2h[i] = make_uint2(pack_h2(wh[k], wh[k + 1]), pack_h2(wh[k + 8], wh[k + 9]));
    }

    const int gb = tid >> 4;
    const int gj = tid & 15;
    const int bg_g = b0 + gb;
    const int jg_g = j0 + gj;
    const float b1r = bhh1[jg_g];
    const float b1z = bhh1[HID + jg_g];
    const float b1n = bhh1[2 * HID + jg_g];
    const float i2r = bih2[jg_g];
    const float i2z = bih2[HID + jg_g];
    const float i2n = bih2[2 * HID + jg_g];
    const float h2r = bhh2[jg_g];
    const float h2z = bhh2[HID + jg_g];
    const float h2n = bhh2[2 * HID + jg_g];

    const int frow = lane >> 2;
    const int fk = lane & 3;
    const int pm = lane >> 2;
    const int pnc = 2 * (lane & 3);

    float hpv1 = __ldg(h0_l1 + (size_t)bg_g * HID + jg_g);
    float hpv2 = __ldg(h0_l2 + (size_t)bg_g * HID + jg_g);

    const float* gxp = gx1_all + (size_t)bg_g * GATES;
    float xr = __ldg(gxp + jg_g);
    float xz = __ldg(gxp + HID + jg_g);
    float xn = __ldg(gxp + 2 * HID + jg_g);

    __syncthreads();   // W2 SMEM ready

    for (int t = 0; t <= T_STEPS; t++) {
        // ================= Layer-1 phase: stage h1[t-1]; full step if t<512
        if (t == 0) {
#pragma unroll
            for (int it = 0; it < 8; it++) {
                int f = it * 32 + lane;
                int rr = f >> 4;
                int c4 = f & 15;
                float4 v = *((const float4*)(h0_l1 + (size_t)(b0 + rr) * HID + w * 64) + c4);
                uint2 u = make_uint2(pack_h2(v.x, v.y), pack_h2(v.z, v.w));
                *(uint2*)&h1_s[rr * HSH_PITCH + w * 64 + c4 * 4] = u;
            }
        } else {
            unsigned target = 4u * (unsigned)t;
            unsigned* cp = &g_cntL[0][bt][w].v;
            while (ld_acq_gpu(cp) < target) { }
            const __half* mir = &g_hmir1[(t - 1) & 1][b0][0];
#pragma unroll
            for (int it = 0; it < 4; it++) {
                int f = it * 32 + lane;
                int rr = f >> 3;
                int c  = f & 7;
                uint32_t dst = (uint32_t)__cvta_generic_to_shared(
                    &h1_s[rr * HSH_PITCH + w * 64 + c * 8]);
                cp_async16(dst, mir + (size_t)rr * HID + w * 64 + c * 8);
            }
            asm volatile("cp.async.commit_group;");
            asm volatile("cp.async.wait_group 0;");
        }

        if (t < T_STEPS) {
            float acc[6][4];
#pragma unroll
            for (int tl = 0; tl < 6; tl++) {
                acc[tl][0] = 0.f; acc[tl][1] = 0.f; acc[tl][2] = 0.f; acc[tl][3] = 0.f;
            }
#pragma unroll
            for (int kk = 0; kk < 4; kk++) {
                int kbase = (w * 4 + kk) * 16;
                uint32_t a0 = *(const uint32_t*)&h1_s[frow * HSH_PITCH + kbase + fk * 2];
                uint32_t a1 = *(const uint32_t*)&h1_s[(frow + 8) * HSH_PITCH + kbase + fk * 2];
                uint32_t a2 = *(const uint32_t*)&h1_s[frow * HSH_PITCH + kbase + 8 + fk * 2];
                uint32_t a3 = *(const uint32_t*)&h1_s[(frow + 8) * HSH_PITCH + kbase + 8 + fk * 2];
#pragma unroll
                for (int tl = 0; tl < 6; tl++)
                    MMA_F16(acc[tl], a0, a1, a2, a3, wb0[tl][kk], wb1[tl][kk]);
            }
#pragma unroll
            for (int tl = 0; tl < 6; tl++) {
                *(float2*)&Ps_a[(w * 16 + pm) * PS_PITCH + tl * 8 + pnc] =
                    make_float2(acc[tl][0], acc[tl][1]);
                *(float2*)&Ps_a[(w * 16 + pm + 8) * PS_PITCH + tl * 8 + pnc] =
                    make_float2(acc[tl][2], acc[tl][3]);
            }
            __syncthreads();

            float hr = 0.f, hz = 0.f, hn = 0.f;
#pragma unroll
            for (int ww = 0; ww < 8; ww++) {
                const float* p = &Ps_a[(ww * 16 + gb) * PS_PITCH];
                hr += p[gj];
                hz += p[16 + gj];
                hn += p[32 + gj];
            }
            float r = 1.0f / (1.0f + __expf(-(xr + hr + b1r)));
            float z = 1.0f / (1.0f + __expf(-(xz + hz + b1z)));
            float n = tanhf(xn + r * (hn + b1n));
            float h1new = (1.0f - z) * n + z * hpv1;
            hpv1 = h1new;

            g_hmir1[t & 1][bg_g][jg_g] = __float2half_rn(h1new);
            __syncthreads();
            if (tid == 0)
                red_add_rel_gpu(&g_cntL[0][bt][my_oct].v);

            // prefetch next gx1
            int tn = (t + 1 < T_STEPS) ? t + 1 : t;
            const float* gxn = gx1_all + (size_t)tn * BATCH * GATES + (size_t)bg_g * GATES;
            xr = __ldg(gxn + jg_g);
            xz = __ldg(gxn + HID + jg_g);
            xn = __ldg(gxn + 2 * HID + jg_g);
        }

        // ================= Layer-2 phase: step s = t-1
        if (t >= 1) {
            const int s = t - 1;
            if (s == 0) {
#pragma unroll
                for (int it = 0; it < 8; it++) {
                    int f = it * 32 + lane;
                    int rr = f >> 4;
                    int c4 = f & 15;
                    float4 v = *((const float4*)(h0_l2 + (size_t)(b0 + rr) * HID + w * 64) + c4);
                    uint2 u = make_uint2(pack_h2(v.x, v.y), pack_h2(v.z, v.w));
                    *(uint2*)&h2_s[rr * HSH_PITCH + w * 64 + c4 * 4] = u;
                }
            } else {
                unsigned target = 4u * (unsigned)s;
                unsigned* cp = &g_cntL[1][bt][w].v;
                while (ld_acq_gpu(cp) < target) { }
                const __half* mir = &g_hmir2[(s - 1) & 1][b0][0];
#pragma unroll
                for (int it = 0; it < 4; it++) {
                    int f = it * 32 + lane;
                    int rr = f >> 3;
                    int c  = f & 7;
                    uint32_t dst = (uint32_t)__cvta_generic_to_shared(
                        &h2_s[rr * HSH_PITCH + w * 64 + c * 8]);
                    cp_async16(dst, mir + (size_t)rr * HID + w * 64 + c * 8);
                }
                asm volatile("cp.async.commit_group;");
                asm volatile("cp.async.wait_group 0;");
            }

            float acc[6][4];
            // ---- input-side: gx2[s] = h1[s] (already staged) @ W_ih2^T
#pragma unroll
            for (int tl = 0; tl < 6; tl++) {
                acc[tl][0] = 0.f; acc[tl][1] = 0.f; acc[tl][2] = 0.f; acc[tl][3] = 0.f;
            }
#pragma unroll
            for (int kk = 0; kk < 4; kk++) {
                int k16g = w * 4 + kk;
                int kbase = k16g * 16;
                uint32_t a0 = *(const uint32_t*)&h1_s[frow * HSH_PITCH + kbase + fk * 2];
                uint32_t a1 = *(const uint32_t*)&h1_s[(frow + 8) * HSH_PITCH + kbase + fk * 2];
                uint32_t a2 = *(const uint32_t*)&h1_s[frow * HSH_PITCH + kbase + 8 + fk * 2];
                uint32_t a3 = *(const uint32_t*)&h1_s[(frow + 8) * HSH_PITCH + kbase + 8 + fk * 2];
#pragma unroll
                for (int tl = 0; tl < 6; tl++) {
                    uint2 bv = W2i[(tl * 32 + k16g) * 32 + lane];
                    MMA_F16(acc[tl], a0, a1, a2, a3, bv.x, bv.y);
                }
            }
#pragma unroll
            for (int tl = 0; tl < 6; tl++) {
                *(float2*)&Ps_a[(w * 16 + pm) * PS_PITCH + tl * 8 + pnc] =
                    make_float2(acc[tl][0], acc[tl][1]);
                *(float2*)&Ps_a[(w * 16 + pm + 8) * PS_PITCH + tl * 8 + pnc] =
                    make_float2(acc[tl][2], acc[tl][3]);
            }
            // ---- recurrent side: h2[s-1] @ W_hh2^T
#pragma unroll
            for (int tl = 0; tl < 6; tl++) {
                acc[tl][0] = 0.f; acc[tl][1] = 0.f; acc[tl][2] = 0.f; acc[tl][3] = 0.f;
            }
#pragma unroll
            for (int kk = 0; kk < 4; kk++) {
                int k16g = w * 4 + kk;
                int kbase = k16g * 16;
                uint32_t a0 = *(const uint32_t*)&h2_s[frow * HSH_PITCH + kbase + fk * 2];
                uint32_t a1 = *(const uint32_t*)&h2_s[(frow + 8) * HSH_PITCH + kbase + fk * 2];
                uint32_t a2 = *(const uint32_t*)&h2_s[frow * HSH_PITCH + kbase + 8 + fk * 2];
                uint32_t a3 = *(const uint32_t*)&h2_s[(frow + 8) * HSH_PITCH + kbase + 8 + fk * 2];
#pragma unroll
                for (int tl = 0; tl < 6; tl++) {
                    uint2 bv = W2h[(tl * 32 + k16g) * 32 + lane];
                    MMA_F16(acc[tl], a0, a1, a2, a3, bv.x, bv.y);
                }
            }
#pragma unroll
            for (int tl = 0; tl < 6; tl++) {
                *(float2*)&Ps_b[(w * 16 + pm) * PS_PITCH + tl * 8 + pnc] =
                    make_float2(acc[tl][0], acc[tl][1]);
                *(float2*)&Ps_b[(w * 16 + pm + 8) * PS_PITCH + tl * 8 + pnc] =
                    make_float2(acc[tl][2], acc[tl][3]);
            }
            __syncthreads();

            float xr2 = 0.f, xz2 = 0.f, xn2 = 0.f;
            float hr2 = 0.f, hz2 = 0.f, hn2 = 0.f;
#pragma unroll
            for (int ww = 0; ww < 8; ww++) {
                const float* pa = &Ps_a[(ww * 16 + gb) * PS_PITCH];
                const float* pb = &Ps_b[(ww * 16 + gb) * PS_PITCH];
                xr2 += pa[gj];  xz2 += pa[16 + gj];  xn2 += pa[32 + gj];
                hr2 += pb[gj];  hz2 += pb[16 + gj];  hn2 += pb[32 + gj];
            }
            float r2 = 1.0f / (1.0f + __expf(-(xr2 + i2r + hr2 + h2r)));
            float z2 = 1.0f / (1.0f + __expf(-(xz2 + i2z + hz2 + h2z)));
            float n2 = tanhf(xn2 + i2n + r2 * (hn2 + h2n));
            float h2new = (1.0f - z2) * n2 + z2 * hpv2;
            hpv2 = h2new;

            g_hmir2[s & 1][bg_g][jg_g] = __float2half_rn(h2new);
            out[(size_t)s * BATCH * HID + (size_t)bg_g * HID + jg_g] = h2new;
            __syncthreads();
            if (tid == 0 && s != T_STEPS - 1)
                red_add_rel_gpu(&g_cntL[1][bt][my_oct].v);
        }
    }

    // end: fence the group, then reset this group's counters (both layers)
    group_barrier(bt, 32);
    if (jt == 0 && tid < 8) {
        *(volatile unsigned*)&g_cntL[0][bt][tid].v = 0;
        *(volatile unsigned*)&g_cntL[1][bt][tid].v = 0;
    }
}

// ---------------------------------------------------------------------------
extern "C" void kernel_launch(void* const* d_in, const int* in_sizes, int n_in,
                              void* d_out, int out_size)
{
    const float* x    = (const float*)d_in[0];
    const float* h0   = (const float*)d_in[1];
    const float* w_ih = (const float*)d_in[2];
    const float* w_hh = (const float*)d_in[3];
    const float* b_ih = (const float*)d_in[4];
    const float* b_hh = (const float*)d_in[5];
    float* out_final  = (float*)d_out;

    float* gates; uint32_t* wfrag;
    cudaGetSymbolAddress((void**)&gates, g_gates);
    cudaGetSymbolAddress((void**)&wfrag, g_wfrag);

    static int smem_configured = 0;
    if (!smem_configured) {
        cudaFuncSetAttribute(gru_fused2,
                             cudaFuncAttributeMaxDynamicSharedMemorySize, FUSED_SMEM_BYTES);
        smem_configured = 1;
    }

    const int M = T_STEPS * BATCH;
    const int K = HID;

    // layer-1 input GEMM (parallel, off the serial path)
    conv_wfrag_h<<<1536, 256>>>(w_ih, wfrag);
    dim3 ggrid(GATES / 128, M / 64);
    gemm_f16<<<ggrid, 256>>>(x, wfrag, b_ih, gates, M, GATES, K);

    // fused 2-layer pipelined recurrence
    gru_fused2<<<128, 256, FUSED_SMEM_BYTES>>>(
        gates, h0,
        w_hh, b_hh,                                   // layer-1 recurrent
        w_ih + (size_t)GATES * HID, b_ih + GATES,     // layer-2 input
        w_hh + (size_t)GATES * HID, b_hh + GATES,     // layer-2 recurrent
        out_final);
}